// round 1
// baseline (speedup 1.0000x reference)
#include <cuda_runtime.h>
#include <math.h>

// ---------------- dims ----------------
static const int Lc = 12, Hc = 12, Dc = 768, HDc = 64, Mc = 3072;
static const int Pc = 16, IMGc = 384, Bc = 32, NCc = 1000;
static const int NP = 576;            // patches
static const int Sc = 577;            // seq len
static const int BS = Bc * Sc;        // 18464
static const int GRID24 = 24;

// ---------------- scratch (device globals; no allocation allowed) ----------------
__device__ float g_t[BS * Dc];            // residual stream
__device__ float g_h[BS * Dc];            // ln outputs (reused as patch gemm out)
__device__ float g_om[BS * Dc];           // attention output merged
__device__ float g_qkv[BS * 3 * Dc];      // [BS, 2304]
__device__ float g_scores[(long long)Bc * Hc * Sc * Sc]; // 384*577*577
__device__ float g_mbuf[BS * Mc];         // mlp intermediate
__device__ float g_col[Bc * NP * Dc];     // im2col
__device__ float g_wtqkv[Lc * Dc * 3 * Dc]; // per-layer [768,2304]
__device__ float g_cwt[Dc * Dc];          // conv weight transposed [k, c]
__device__ float g_cls[Bc * Dc];

// ---------------- generic tiled SGEMM ----------------
// C[M,N] = act( alpha * A@B(^T) + bias + res )
// batched over gridDim.z; z decomposed as (zb = z/zdiv, zh = z%zdiv)
template <int TB>
__global__ void sgemm_kernel(const float* __restrict__ A, const float* __restrict__ Bm,
                             const float* __restrict__ bias, const float* __restrict__ res,
                             float* __restrict__ C,
                             int M, int N, int K, int lda, int ldb, int ldc,
                             long long sAb, long long sAh, long long sBb, long long sBh,
                             long long sCb, long long sCh, int zdiv,
                             float alpha, int act) {
    __shared__ float As[16][68];
    __shared__ float Bs[16][68];

    int z = blockIdx.z;
    int zb = z / zdiv, zh = z % zdiv;
    A  += zb * sAb + zh * sAh;
    Bm += zb * sBb + zh * sBh;
    C  += zb * sCb + zh * sCh;
    if (res) res += zb * sCb + zh * sCh;

    int t = threadIdx.x;
    int tx = t & 15, ty = t >> 4;
    int m0 = blockIdx.y * 64, n0 = blockIdx.x * 64;

    float acc[4][4];
#pragma unroll
    for (int i = 0; i < 4; i++)
#pragma unroll
        for (int j = 0; j < 4; j++) acc[i][j] = 0.f;

    for (int k0 = 0; k0 < K; k0 += 16) {
        // A tile: As[k][m]
#pragma unroll
        for (int i = 0; i < 4; i++) {
            int q = t + i * 256;
            int kk = q & 15, mm = q >> 4;
            int gm = m0 + mm, gk = k0 + kk;
            As[kk][mm] = (gm < M && gk < K) ? A[(long long)gm * lda + gk] : 0.f;
        }
        // B tile: Bs[k][n]
#pragma unroll
        for (int i = 0; i < 4; i++) {
            if (TB == 0) {
                int q = t + i * 256;
                int nn = q & 63, kk = q >> 6;
                int gn = n0 + nn, gk = k0 + kk;
                Bs[kk][nn] = (gn < N && gk < K) ? Bm[(long long)gk * ldb + gn] : 0.f;
            } else {
                int q = t + i * 256;
                int kk = q & 15, nn = q >> 4;
                int gn = n0 + nn, gk = k0 + kk;
                Bs[kk][nn] = (gn < N && gk < K) ? Bm[(long long)gn * ldb + gk] : 0.f;
            }
        }
        __syncthreads();
#pragma unroll
        for (int kk = 0; kk < 16; kk++) {
            float4 a4 = *(const float4*)&As[kk][ty * 4];
            float4 b4 = *(const float4*)&Bs[kk][tx * 4];
            float a[4] = {a4.x, a4.y, a4.z, a4.w};
            float b[4] = {b4.x, b4.y, b4.z, b4.w};
#pragma unroll
            for (int i = 0; i < 4; i++)
#pragma unroll
                for (int j = 0; j < 4; j++) acc[i][j] += a[i] * b[j];
        }
        __syncthreads();
    }

#pragma unroll
    for (int i = 0; i < 4; i++) {
        int m = m0 + ty * 4 + i;
        if (m >= M) continue;
#pragma unroll
        for (int j = 0; j < 4; j++) {
            int n = n0 + tx * 4 + j;
            if (n >= N) continue;
            float v = acc[i][j] * alpha;
            if (bias) v += bias[n];
            if (res) v += res[(long long)m * ldc + n];
            if (act == 1) v = 0.5f * v * (1.0f + erff(v * 0.7071067811865476f));
            C[(long long)m * ldc + n] = v;
        }
    }
}

// ---------------- aux kernels ----------------
__global__ void im2col_kernel(const float* __restrict__ x, float* __restrict__ col) {
    long long idx = (long long)blockIdx.x * blockDim.x + threadIdx.x;
    long long total = (long long)Bc * NP * Dc;
    if (idx >= total) return;
    int k = (int)(idx % Dc);
    int rem = (int)(idx / Dc);
    int p = rem % NP;
    int b = rem / NP;
    int ph = p / GRID24, pw = p % GRID24;
    int ci = k / 256, k2 = k % 256;
    int kh = k2 / 16, kw = k2 % 16;
    col[idx] = x[(((long long)b * 3 + ci) * IMGc + ph * 16 + kh) * IMGc + pw * 16 + kw];
}

__global__ void transpose_convw_kernel(const float* __restrict__ w, float* __restrict__ wt) {
    int idx = blockIdx.x * blockDim.x + threadIdx.x;
    if (idx >= Dc * Dc) return;
    int k = idx / Dc, c = idx % Dc;
    wt[idx] = w[c * Dc + k];  // conv_w [c_out, 768(k)] -> [k, c_out]
}

__global__ void transpose_wqkv_kernel(const float* __restrict__ w, float* __restrict__ wt) {
    long long idx = (long long)blockIdx.x * blockDim.x + threadIdx.x;
    long long total = (long long)Lc * Dc * 3 * Dc;
    if (idx >= total) return;
    int n = (int)(idx % (3 * Dc));
    int rem = (int)(idx / (3 * Dc));
    int d = rem % Dc;
    int l = rem / Dc;
    int h = n / 192, e = n % 192;
    wt[idx] = w[(((long long)l * Hc + h) * Dc + d) * 192 + e];
}

// build t[B,577,768] from patch gemm out (channel-major flatten), cls, pos
__global__ void embed_kernel(const float* __restrict__ pout, const float* __restrict__ cls,
                             const float* __restrict__ pos, float* __restrict__ t) {
    long long idx = (long long)blockIdx.x * blockDim.x + threadIdx.x;
    long long total = (long long)Bc * Sc * Dc;
    if (idx >= total) return;
    int j = (int)(idx % Dc);
    int rem = (int)(idx / Dc);
    int r = rem % Sc;
    int b = rem / Sc;
    float v;
    if (r == 0) {
        v = cls[j];
    } else {
        int i = (r - 1) * Dc + j;
        int c = i / NP, p = i % NP;
        v = pout[((long long)b * NP + p) * Dc + c];
    }
    t[idx] = v + pos[r * Dc + j];
}

// layernorm: one block per row, D=768, 256 threads
__global__ void layernorm_kernel(const float* __restrict__ x, const float* __restrict__ g,
                                 const float* __restrict__ b, float* __restrict__ y, int rows) {
    __shared__ float red[256];
    int row = blockIdx.x;
    if (row >= rows) return;
    int t = threadIdx.x;
    const float* xr = x + (long long)row * Dc;
    float v[3];
    float s = 0.f;
#pragma unroll
    for (int i = 0; i < 3; i++) { v[i] = xr[t + i * 256]; s += v[i]; }
    red[t] = s; __syncthreads();
    for (int o = 128; o > 0; o >>= 1) { if (t < o) red[t] += red[t + o]; __syncthreads(); }
    float mu = red[0] / Dc;
    __syncthreads();
    float s2 = 0.f;
#pragma unroll
    for (int i = 0; i < 3; i++) { float d = v[i] - mu; s2 += d * d; }
    red[t] = s2; __syncthreads();
    for (int o = 128; o > 0; o >>= 1) { if (t < o) red[t] += red[t + o]; __syncthreads(); }
    float rstd = rsqrtf(red[0] / Dc + 1e-5f);
    float* yr = y + (long long)row * Dc;
#pragma unroll
    for (int i = 0; i < 3; i++) {
        int j = t + i * 256;
        yr[j] = (v[i] - mu) * rstd * g[j] + b[j];
    }
}

// row softmax, n <= 1024, block per row, 256 threads
__global__ void softmax_kernel(float* __restrict__ x, long long rows, int n) {
    __shared__ float red[256];
    long long row = blockIdx.x;
    if (row >= rows) return;
    int t = threadIdx.x;
    float* xr = x + row * n;
    float lmax = -1e30f;
    for (int j = t; j < n; j += 256) lmax = fmaxf(lmax, xr[j]);
    red[t] = lmax; __syncthreads();
    for (int o = 128; o > 0; o >>= 1) { if (t < o) red[t] = fmaxf(red[t], red[t + o]); __syncthreads(); }
    float mx = red[0];
    __syncthreads();
    float ls = 0.f;
    for (int j = t; j < n; j += 256) { float e = expf(xr[j] - mx); xr[j] = e; ls += e; }
    red[t] = ls; __syncthreads();
    for (int o = 128; o > 0; o >>= 1) { if (t < o) red[t] += red[t + o]; __syncthreads(); }
    float inv = 1.0f / red[0];
    for (int j = t; j < n; j += 256) xr[j] *= inv;
}

__global__ void extract_cls_kernel(const float* __restrict__ t, float* __restrict__ cls) {
    int idx = blockIdx.x * blockDim.x + threadIdx.x;
    if (idx >= Bc * Dc) return;
    int b = idx / Dc, j = idx % Dc;
    cls[idx] = t[((long long)b * Sc) * Dc + j];
}

// ---------------- host helpers ----------------
static void run_gemm(bool transB, const float* A, const float* Bm, const float* bias,
                     const float* res, float* C, int M, int N, int K,
                     int lda, int ldb, int ldc, int Z, int zdiv,
                     long long sAb, long long sAh, long long sBb, long long sBh,
                     long long sCb, long long sCh, float alpha, int act) {
    dim3 grid((N + 63) / 64, (M + 63) / 64, Z);
    if (transB)
        sgemm_kernel<1><<<grid, 256>>>(A, Bm, bias, res, C, M, N, K, lda, ldb, ldc,
                                       sAb, sAh, sBb, sBh, sCb, sCh, zdiv, alpha, act);
    else
        sgemm_kernel<0><<<grid, 256>>>(A, Bm, bias, res, C, M, N, K, lda, ldb, ldc,
                                       sAb, sAh, sBb, sBh, sCb, sCh, zdiv, alpha, act);
}

extern "C" void kernel_launch(void* const* d_in, const int* in_sizes, int n_in,
                              void* d_out, int out_size) {
    const float* x       = (const float*)d_in[0];
    const float* conv_w  = (const float*)d_in[1];
    const float* conv_b  = (const float*)d_in[2];
    const float* cls_tok = (const float*)d_in[3];
    const float* pos_emb = (const float*)d_in[4];
    const float* ln1_g   = (const float*)d_in[5];
    const float* ln1_b   = (const float*)d_in[6];
    const float* wqkv    = (const float*)d_in[7];
    const float* bqkv    = (const float*)d_in[8];
    const float* wmsa    = (const float*)d_in[9];
    const float* bmsa    = (const float*)d_in[10];
    const float* ln2_g   = (const float*)d_in[11];
    const float* ln2_b   = (const float*)d_in[12];
    const float* lnm_g   = (const float*)d_in[13];
    const float* lnm_b   = (const float*)d_in[14];
    const float* w1      = (const float*)d_in[15];
    const float* b1      = (const float*)d_in[16];
    const float* w2      = (const float*)d_in[17];
    const float* b2      = (const float*)d_in[18];
    const float* lnf_g   = (const float*)d_in[19];
    const float* lnf_b   = (const float*)d_in[20];
    const float* whead   = (const float*)d_in[21];
    const float* bhead   = (const float*)d_in[22];
    float* out = (float*)d_out;

    float *t_, *h_, *om_, *qkv_, *sc_, *mb_, *col_, *wtq_, *cwt_, *cls_;
    cudaGetSymbolAddress((void**)&t_,  g_t);
    cudaGetSymbolAddress((void**)&h_,  g_h);
    cudaGetSymbolAddress((void**)&om_, g_om);
    cudaGetSymbolAddress((void**)&qkv_, g_qkv);
    cudaGetSymbolAddress((void**)&sc_, g_scores);
    cudaGetSymbolAddress((void**)&mb_, g_mbuf);
    cudaGetSymbolAddress((void**)&col_, g_col);
    cudaGetSymbolAddress((void**)&wtq_, g_wtqkv);
    cudaGetSymbolAddress((void**)&cwt_, g_cwt);
    cudaGetSymbolAddress((void**)&cls_, g_cls);

    // --- weight re-layouts (cheap, graph-capturable) ---
    transpose_convw_kernel<<<(Dc * Dc + 255) / 256, 256>>>(conv_w, cwt_);
    {
        long long tot = (long long)Lc * Dc * 3 * Dc;
        transpose_wqkv_kernel<<<(int)((tot + 255) / 256), 256>>>(wqkv, wtq_);
    }

    // --- patchify: im2col + GEMM + embed assemble ---
    {
        long long tot = (long long)Bc * NP * Dc;
        im2col_kernel<<<(int)((tot + 255) / 256), 256>>>(x, col_);
    }
    run_gemm(false, col_, cwt_, conv_b, nullptr, h_, Bc * NP, Dc, Dc, Dc, Dc, Dc,
             1, 1, 0, 0, 0, 0, 0, 0, 1.0f, 0);
    {
        long long tot = (long long)Bc * Sc * Dc;
        embed_kernel<<<(int)((tot + 255) / 256), 256>>>(h_, cls_tok, pos_emb, t_);
    }

    // --- encoder layers ---
    for (int l = 0; l < Lc; l++) {
        // ln1: t -> h
        layernorm_kernel<<<BS, 256>>>(t_, ln1_g + l * Dc, ln1_b + l * Dc, h_, BS);
        // qkv = h @ Wt[l] + bqkv[l]    [BS, 2304]
        run_gemm(false, h_, wtq_ + (long long)l * Dc * 3 * Dc, bqkv + l * 3 * Dc, nullptr,
                 qkv_, BS, 3 * Dc, Dc, Dc, 3 * Dc, 3 * Dc, 1, 1, 0, 0, 0, 0, 0, 0, 1.0f, 0);
        // scores[b,h] = SCALE * Q @ K^T    (z = b*H + h)
        run_gemm(true, qkv_, qkv_ + HDc, nullptr, nullptr, sc_,
                 Sc, Sc, HDc, 3 * Dc, 3 * Dc, Sc, Bc * Hc, Hc,
                 (long long)Sc * 3 * Dc, 192, (long long)Sc * 3 * Dc, 192,
                 (long long)Hc * Sc * Sc, (long long)Sc * Sc, 0.125f, 0);
        // softmax rows
        softmax_kernel<<<(unsigned)((long long)Bc * Hc * Sc), 256>>>(sc_, (long long)Bc * Hc * Sc, Sc);
        // O = P @ V  -> head-merged layout om[b, s, h*64+e]
        run_gemm(false, sc_, qkv_ + 128, nullptr, nullptr, om_,
                 Sc, HDc, Sc, Sc, 3 * Dc, Dc, Bc * Hc, Hc,
                 (long long)Hc * Sc * Sc, (long long)Sc * Sc,
                 (long long)Sc * 3 * Dc, 192,
                 (long long)Sc * Dc, HDc, 1.0f, 0);
        // msa: t = om @ wmsa[l] + bmsa[l] + h (residual around post-LN1)
        run_gemm(false, om_, wmsa + (long long)l * Dc * Dc, bmsa + l * Dc, h_, t_,
                 BS, Dc, Dc, Dc, Dc, Dc, 1, 1, 0, 0, 0, 0, 0, 0, 1.0f, 0);
        // ln2: t -> h, then lnm: h -> h (faithful double LN)
        layernorm_kernel<<<BS, 256>>>(t_, ln2_g + l * Dc, ln2_b + l * Dc, h_, BS);
        layernorm_kernel<<<BS, 256>>>(h_, lnm_g + l * Dc, lnm_b + l * Dc, h_, BS);
        // mlp1: mb = gelu(h @ w1[l] + b1[l])
        run_gemm(false, h_, w1 + (long long)l * Dc * Mc, b1 + l * Mc, nullptr, mb_,
                 BS, Mc, Dc, Dc, Mc, Mc, 1, 1, 0, 0, 0, 0, 0, 0, 1.0f, 1);
        // mlp2: t = mb @ w2[l] + b2[l] + t
        run_gemm(false, mb_, w2 + (long long)l * Mc * Dc, b2 + l * Dc, t_, t_,
                 BS, Dc, Mc, Mc, Dc, Dc, 1, 1, 0, 0, 0, 0, 0, 0, 1.0f, 0);
    }

    // --- head ---
    extract_cls_kernel<<<(Bc * Dc + 255) / 256, 256>>>(t_, cls_);
    layernorm_kernel<<<Bc, 256>>>(cls_, lnf_g, lnf_b, cls_, Bc);
    run_gemm(false, cls_, whead, bhead, nullptr, out,
             Bc, NCc, Dc, Dc, NCc, NCc, 1, 1, 0, 0, 0, 0, 0, 0, 1.0f, 0);
    softmax_kernel<<<Bc, 256>>>(out, Bc, NCc);
}

// round 2
// speedup vs baseline: 2.9795x; 2.9795x over previous
#include <cuda_runtime.h>
#include <math.h>
#include <stdint.h>

// ---------------- dims ----------------
static const int Lc = 12, Hc = 12, Dc = 768, HDc = 64, Mc = 3072;
static const int IMGc = 384, Bc = 32, NCc = 1000;
static const int NP = 576;            // patches
static const int Sc = 577;            // seq len
static const int SLD = 592;           // padded score row stride (multiple of 16)
static const int BS = Bc * Sc;        // 18464
static const int GRID24 = 24;

// ---------------- scratch (device globals; no allocation allowed) ----------------
__device__ float g_t[BS * Dc];                 // residual stream
__device__ float g_h[BS * Dc];                 // ln outputs / patch gemm out
__device__ float g_om[BS * Dc];                // attention output merged
__device__ float g_qkv[(BS + 16) * 3 * Dc];    // [BS,2304] + 16 pad rows (PV k-overread)
__device__ float g_scores[(long long)Bc * Hc * Sc * SLD];
__device__ float g_mbuf[BS * Mc];              // mlp intermediate
__device__ float g_col[Bc * NP * Dc];          // im2col
__device__ float g_wtqkv[Lc * Dc * 3 * Dc];    // per-layer [768,2304]
__device__ float g_cwt[Dc * Dc];               // conv weight transposed
__device__ float g_cls[Bc * Dc];

// ---------------- tf32 mma helpers ----------------
__device__ __forceinline__ uint32_t f2tf(float f) {
    uint32_t u;
    asm("cvt.rna.tf32.f32 %0, %1;" : "=r"(u) : "f"(f));
    return u;
}

__device__ __forceinline__ void mma_tf32(float c[4], const uint32_t a[4], const uint32_t b[2]) {
    asm volatile(
        "mma.sync.aligned.m16n8k8.row.col.f32.tf32.tf32.f32 "
        "{%0,%1,%2,%3}, {%4,%5,%6,%7}, {%8,%9}, {%0,%1,%2,%3};\n"
        : "+f"(c[0]), "+f"(c[1]), "+f"(c[2]), "+f"(c[3])
        : "r"(a[0]), "r"(a[1]), "r"(a[2]), "r"(a[3]), "r"(b[0]), "r"(b[1]));
}

__device__ __forceinline__ void cp_async16(void* smem_dst, const void* gsrc, int sz) {
    unsigned sm = (unsigned)__cvta_generic_to_shared(smem_dst);
    asm volatile("cp.async.ca.shared.global [%0], [%1], 16, %2;\n" :: "r"(sm), "l"(gsrc), "r"(sz));
}

// ---------------- tf32 tensor-core GEMM ----------------
// C[M,N] = act( alpha * A@B(^T) + bias + res ), batched over z (zb,zh)
// CTA tile 128x128, BK=16, 8 warps (2x4), warp tile 64x32.
template <int TB>
__global__ void __launch_bounds__(256)
mma_gemm_kernel(const float* __restrict__ A, const float* __restrict__ Bm,
                const float* __restrict__ bias, const float* __restrict__ res,
                float* __restrict__ C,
                int M, int N, int K, int lda, int ldb, int ldc,
                long long sAb, long long sAh, long long sBb, long long sBh,
                long long sCb, long long sCh, int zdiv,
                float alpha, int act) {
    __shared__ float As[2][128][20];    // [m][k], pad to 20 (conflict-free frag loads)
    __shared__ float Bs[2][16][136];    // [k][n], pad to 136

    int z = blockIdx.z;
    int zb = z / zdiv, zh = z % zdiv;
    A  += zb * sAb + zh * sAh;
    Bm += zb * sBb + zh * sBh;
    C  += zb * sCb + zh * sCh;
    if (res) res += zb * sCb + zh * sCh;

    int t = threadIdx.x;
    int lane = t & 31, wid = t >> 5;
    int wm = wid >> 2, wn = wid & 3;        // 2 x 4 warp grid
    int g = lane >> 2, tig = lane & 3;
    int m0 = blockIdx.y * 128, n0 = blockIdx.x * 128;

    float acc[4][4][4] = {};                // [mt][nt][c]

    int nk = (K + 15) / 16;

    auto loadA = [&](int k0, int buf) {
#pragma unroll
        for (int i = 0; i < 2; i++) {
            int c = t + i * 256;
            int m = c >> 2, kq = (c & 3) * 4;
            const float* src = A + (long long)(m0 + m) * lda + k0 + kq;
            int sz = (m0 + m < M) ? 16 : 0;   // k always readable (K mult of 16 or padded rows)
            cp_async16(&As[buf][m][kq], src, sz);
        }
    };
    auto loadB_async = [&](int k0, int buf) {   // TB==0: B row-major [k][n]
#pragma unroll
        for (int i = 0; i < 2; i++) {
            int c = t + i * 256;
            int k = c >> 5, nq = (c & 31) * 4;
            const float* src = Bm + (long long)(k0 + k) * ldb + n0 + nq;
            int sz = (n0 + nq < N && k0 + k < K) ? 16 : 0;
            cp_async16(&Bs[buf][k][nq], src, sz);
        }
    };
    auto loadB_plain = [&](int k0, int buf) {   // TB==1: B is [n][k]; transpose into Bs
#pragma unroll
        for (int i = 0; i < 2; i++) {
            int c = t + i * 256;
            int n = c >> 2, kq = (c & 3) * 4;
            float4 v = make_float4(0.f, 0.f, 0.f, 0.f);
            if (n0 + n < N)
                v = *(const float4*)(Bm + (long long)(n0 + n) * ldb + k0 + kq);
            Bs[buf][kq + 0][n] = v.x;
            Bs[buf][kq + 1][n] = v.y;
            Bs[buf][kq + 2][n] = v.z;
            Bs[buf][kq + 3][n] = v.w;
        }
    };

    // prologue: stage 0
    loadA(0, 0);
    if (TB == 0) loadB_async(0, 0);
    asm volatile("cp.async.commit_group;\n");
    if (TB == 1) loadB_plain(0, 0);
    asm volatile("cp.async.wait_group 0;\n");
    __syncthreads();

    for (int it = 0; it < nk; it++) {
        int buf = it & 1;
        if (it + 1 < nk) {
            loadA((it + 1) * 16, buf ^ 1);
            if (TB == 0) loadB_async((it + 1) * 16, buf ^ 1);
            asm volatile("cp.async.commit_group;\n");
            if (TB == 1) loadB_plain((it + 1) * 16, buf ^ 1);
        }
#pragma unroll
        for (int ks = 0; ks < 2; ks++) {
            int kk = ks * 8;
            uint32_t af[4][4], bf[4][2];
#pragma unroll
            for (int mt = 0; mt < 4; mt++) {
                int mr = wm * 64 + mt * 16 + g;
                af[mt][0] = f2tf(As[buf][mr][kk + tig]);
                af[mt][1] = f2tf(As[buf][mr + 8][kk + tig]);
                af[mt][2] = f2tf(As[buf][mr][kk + tig + 4]);
                af[mt][3] = f2tf(As[buf][mr + 8][kk + tig + 4]);
            }
#pragma unroll
            for (int nt = 0; nt < 4; nt++) {
                int nc = wn * 32 + nt * 8 + g;
                bf[nt][0] = f2tf(Bs[buf][kk + tig][nc]);
                bf[nt][1] = f2tf(Bs[buf][kk + tig + 4][nc]);
            }
#pragma unroll
            for (int mt = 0; mt < 4; mt++)
#pragma unroll
                for (int nt = 0; nt < 4; nt++)
                    mma_tf32(acc[mt][nt], af[mt], bf[nt]);
        }
        asm volatile("cp.async.wait_group 0;\n");
        __syncthreads();
    }

    // epilogue
#pragma unroll
    for (int mt = 0; mt < 4; mt++) {
#pragma unroll
        for (int nt = 0; nt < 4; nt++) {
            int row = m0 + wm * 64 + mt * 16 + g;
            int col = n0 + wn * 32 + nt * 8 + tig * 2;
#pragma unroll
            for (int cc = 0; cc < 4; cc++) {
                int m = row + (cc >> 1) * 8;
                int n = col + (cc & 1);
                if (m >= M || n >= N) continue;
                float v = acc[mt][nt][cc] * alpha;
                if (bias) v += bias[n];
                if (res) v += res[(long long)m * ldc + n];
                if (act == 1) v = 0.5f * v * (1.0f + erff(v * 0.7071067811865476f));
                C[(long long)m * ldc + n] = v;
            }
        }
    }
}

// ---------------- aux kernels ----------------
__global__ void im2col_kernel(const float* __restrict__ x, float* __restrict__ col) {
    long long idx = (long long)blockIdx.x * blockDim.x + threadIdx.x;
    long long total = (long long)Bc * NP * Dc;
    if (idx >= total) return;
    int k = (int)(idx % Dc);
    int rem = (int)(idx / Dc);
    int p = rem % NP;
    int b = rem / NP;
    int ph = p / GRID24, pw = p % GRID24;
    int ci = k / 256, k2 = k % 256;
    int kh = k2 / 16, kw = k2 % 16;
    col[idx] = x[(((long long)b * 3 + ci) * IMGc + ph * 16 + kh) * IMGc + pw * 16 + kw];
}

__global__ void transpose_convw_kernel(const float* __restrict__ w, float* __restrict__ wt) {
    int idx = blockIdx.x * blockDim.x + threadIdx.x;
    if (idx >= Dc * Dc) return;
    int k = idx / Dc, c = idx % Dc;
    wt[idx] = w[c * Dc + k];
}

__global__ void transpose_wqkv_kernel(const float* __restrict__ w, float* __restrict__ wt) {
    long long idx = (long long)blockIdx.x * blockDim.x + threadIdx.x;
    long long total = (long long)Lc * Dc * 3 * Dc;
    if (idx >= total) return;
    int n = (int)(idx % (3 * Dc));
    int rem = (int)(idx / (3 * Dc));
    int d = rem % Dc;
    int l = rem / Dc;
    int h = n / 192, e = n % 192;
    wt[idx] = w[(((long long)l * Hc + h) * Dc + d) * 192 + e];
}

__global__ void embed_kernel(const float* __restrict__ pout, const float* __restrict__ cls,
                             const float* __restrict__ pos, float* __restrict__ t) {
    long long idx = (long long)blockIdx.x * blockDim.x + threadIdx.x;
    long long total = (long long)Bc * Sc * Dc;
    if (idx >= total) return;
    int j = (int)(idx % Dc);
    int rem = (int)(idx / Dc);
    int r = rem % Sc;
    int b = rem / Sc;
    float v;
    if (r == 0) {
        v = cls[j];
    } else {
        int i = (r - 1) * Dc + j;
        int c = i / NP, p = i % NP;
        v = pout[((long long)b * NP + p) * Dc + c];
    }
    t[idx] = v + pos[r * Dc + j];
}

__global__ void layernorm_kernel(const float* __restrict__ x, const float* __restrict__ g,
                                 const float* __restrict__ b, float* __restrict__ y, int rows) {
    __shared__ float red[256];
    int row = blockIdx.x;
    if (row >= rows) return;
    int t = threadIdx.x;
    const float* xr = x + (long long)row * Dc;
    float v[3];
    float s = 0.f;
#pragma unroll
    for (int i = 0; i < 3; i++) { v[i] = xr[t + i * 256]; s += v[i]; }
    red[t] = s; __syncthreads();
    for (int o = 128; o > 0; o >>= 1) { if (t < o) red[t] += red[t + o]; __syncthreads(); }
    float mu = red[0] / Dc;
    __syncthreads();
    float s2 = 0.f;
#pragma unroll
    for (int i = 0; i < 3; i++) { float d = v[i] - mu; s2 += d * d; }
    red[t] = s2; __syncthreads();
    for (int o = 128; o > 0; o >>= 1) { if (t < o) red[t] += red[t + o]; __syncthreads(); }
    float rstd = rsqrtf(red[0] / Dc + 1e-5f);
    float* yr = y + (long long)row * Dc;
#pragma unroll
    for (int i = 0; i < 3; i++) {
        int j = t + i * 256;
        yr[j] = (v[i] - mu) * rstd * g[j] + b[j];
    }
}

// softmax on rows of stride ld, active width n; zero-fills [n, ld)
__global__ void softmax_kernel(float* __restrict__ x, long long rows, int n, int ld) {
    __shared__ float red[256];
    long long row = blockIdx.x;
    if (row >= rows) return;
    int t = threadIdx.x;
    float* xr = x + row * ld;
    float lmax = -1e30f;
    for (int j = t; j < n; j += 256) lmax = fmaxf(lmax, xr[j]);
    red[t] = lmax; __syncthreads();
    for (int o = 128; o > 0; o >>= 1) { if (t < o) red[t] = fmaxf(red[t], red[t + o]); __syncthreads(); }
    float mx = red[0];
    __syncthreads();
    float ls = 0.f;
    for (int j = t; j < n; j += 256) { float e = expf(xr[j] - mx); xr[j] = e; ls += e; }
    red[t] = ls; __syncthreads();
    for (int o = 128; o > 0; o >>= 1) { if (t < o) red[t] += red[t + o]; __syncthreads(); }
    float inv = 1.0f / red[0];
    for (int j = t; j < n; j += 256) xr[j] *= inv;
    for (int j = n + t; j < ld; j += 256) xr[j] = 0.f;
}

__global__ void extract_cls_kernel(const float* __restrict__ t, float* __restrict__ cls) {
    int idx = blockIdx.x * blockDim.x + threadIdx.x;
    if (idx >= Bc * Dc) return;
    int b = idx / Dc, j = idx % Dc;
    cls[idx] = t[((long long)b * Sc) * Dc + j];
}

// ---------------- host helpers ----------------
static void run_gemm(bool transB, const float* A, const float* Bm, const float* bias,
                     const float* res, float* C, int M, int N, int K,
                     int lda, int ldb, int ldc, int Z, int zdiv,
                     long long sAb, long long sAh, long long sBb, long long sBh,
                     long long sCb, long long sCh, float alpha, int act) {
    dim3 grid((N + 127) / 128, (M + 127) / 128, Z);
    if (transB)
        mma_gemm_kernel<1><<<grid, 256>>>(A, Bm, bias, res, C, M, N, K, lda, ldb, ldc,
                                          sAb, sAh, sBb, sBh, sCb, sCh, zdiv, alpha, act);
    else
        mma_gemm_kernel<0><<<grid, 256>>>(A, Bm, bias, res, C, M, N, K, lda, ldb, ldc,
                                          sAb, sAh, sBb, sBh, sCb, sCh, zdiv, alpha, act);
}

extern "C" void kernel_launch(void* const* d_in, const int* in_sizes, int n_in,
                              void* d_out, int out_size) {
    const float* x       = (const float*)d_in[0];
    const float* conv_w  = (const float*)d_in[1];
    const float* conv_b  = (const float*)d_in[2];
    const float* cls_tok = (const float*)d_in[3];
    const float* pos_emb = (const float*)d_in[4];
    const float* ln1_g   = (const float*)d_in[5];
    const float* ln1_b   = (const float*)d_in[6];
    const float* wqkv    = (const float*)d_in[7];
    const float* bqkv    = (const float*)d_in[8];
    const float* wmsa    = (const float*)d_in[9];
    const float* bmsa    = (const float*)d_in[10];
    const float* ln2_g   = (const float*)d_in[11];
    const float* ln2_b   = (const float*)d_in[12];
    const float* lnm_g   = (const float*)d_in[13];
    const float* lnm_b   = (const float*)d_in[14];
    const float* w1      = (const float*)d_in[15];
    const float* b1      = (const float*)d_in[16];
    const float* w2      = (const float*)d_in[17];
    const float* b2      = (const float*)d_in[18];
    const float* lnf_g   = (const float*)d_in[19];
    const float* lnf_b   = (const float*)d_in[20];
    const float* whead   = (const float*)d_in[21];
    const float* bhead   = (const float*)d_in[22];
    float* out = (float*)d_out;

    float *t_, *h_, *om_, *qkv_, *sc_, *mb_, *col_, *wtq_, *cwt_, *cls_;
    cudaGetSymbolAddress((void**)&t_,  g_t);
    cudaGetSymbolAddress((void**)&h_,  g_h);
    cudaGetSymbolAddress((void**)&om_, g_om);
    cudaGetSymbolAddress((void**)&qkv_, g_qkv);
    cudaGetSymbolAddress((void**)&sc_, g_scores);
    cudaGetSymbolAddress((void**)&mb_, g_mbuf);
    cudaGetSymbolAddress((void**)&col_, g_col);
    cudaGetSymbolAddress((void**)&wtq_, g_wtqkv);
    cudaGetSymbolAddress((void**)&cwt_, g_cwt);
    cudaGetSymbolAddress((void**)&cls_, g_cls);

    // --- weight re-layouts ---
    transpose_convw_kernel<<<(Dc * Dc + 255) / 256, 256>>>(conv_w, cwt_);
    {
        long long tot = (long long)Lc * Dc * 3 * Dc;
        transpose_wqkv_kernel<<<(int)((tot + 255) / 256), 256>>>(wqkv, wtq_);
    }

    // --- patchify ---
    {
        long long tot = (long long)Bc * NP * Dc;
        im2col_kernel<<<(int)((tot + 255) / 256), 256>>>(x, col_);
    }
    run_gemm(false, col_, cwt_, conv_b, nullptr, h_, Bc * NP, Dc, Dc, Dc, Dc, Dc,
             1, 1, 0, 0, 0, 0, 0, 0, 1.0f, 0);
    {
        long long tot = (long long)Bc * Sc * Dc;
        embed_kernel<<<(int)((tot + 255) / 256), 256>>>(h_, cls_tok, pos_emb, t_);
    }

    // --- encoder layers ---
    for (int l = 0; l < Lc; l++) {
        layernorm_kernel<<<BS, 256>>>(t_, ln1_g + l * Dc, ln1_b + l * Dc, h_, BS);
        // qkv = h @ Wt[l] + bqkv[l]
        run_gemm(false, h_, wtq_ + (long long)l * Dc * 3 * Dc, bqkv + l * 3 * Dc, nullptr,
                 qkv_, BS, 3 * Dc, Dc, Dc, 3 * Dc, 3 * Dc, 1, 1, 0, 0, 0, 0, 0, 0, 1.0f, 0);
        // scores = SCALE * Q @ K^T   (z = b*H + h), padded ldc=SLD
        run_gemm(true, qkv_, qkv_ + HDc, nullptr, nullptr, sc_,
                 Sc, Sc, HDc, 3 * Dc, 3 * Dc, SLD, Bc * Hc, Hc,
                 (long long)Sc * 3 * Dc, 192, (long long)Sc * 3 * Dc, 192,
                 (long long)Hc * Sc * SLD, (long long)Sc * SLD, 0.125f, 0);
        softmax_kernel<<<(unsigned)((long long)Bc * Hc * Sc), 256>>>(
            sc_, (long long)Bc * Hc * Sc, Sc, SLD);
        // O = P @ V  (K padded to 592 with zero score cols; qkv over-allocated)
        run_gemm(false, sc_, qkv_ + 128, nullptr, nullptr, om_,
                 Sc, HDc, Sc, SLD, 3 * Dc, Dc, Bc * Hc, Hc,
                 (long long)Hc * Sc * SLD, (long long)Sc * SLD,
                 (long long)Sc * 3 * Dc, 192,
                 (long long)Sc * Dc, HDc, 1.0f, 0);
        // msa: t = om @ wmsa + bmsa + h
        run_gemm(false, om_, wmsa + (long long)l * Dc * Dc, bmsa + l * Dc, h_, t_,
                 BS, Dc, Dc, Dc, Dc, Dc, 1, 1, 0, 0, 0, 0, 0, 0, 1.0f, 0);
        // double LN
        layernorm_kernel<<<BS, 256>>>(t_, ln2_g + l * Dc, ln2_b + l * Dc, h_, BS);
        layernorm_kernel<<<BS, 256>>>(h_, lnm_g + l * Dc, lnm_b + l * Dc, h_, BS);
        // mlp
        run_gemm(false, h_, w1 + (long long)l * Dc * Mc, b1 + l * Mc, nullptr, mb_,
                 BS, Mc, Dc, Dc, Mc, Mc, 1, 1, 0, 0, 0, 0, 0, 0, 1.0f, 1);
        run_gemm(false, mb_, w2 + (long long)l * Mc * Dc, b2 + l * Dc, t_, t_,
                 BS, Dc, Mc, Mc, Dc, Dc, 1, 1, 0, 0, 0, 0, 0, 0, 1.0f, 0);
    }

    // --- head ---
    extract_cls_kernel<<<(Bc * Dc + 255) / 256, 256>>>(t_, cls_);
    layernorm_kernel<<<Bc, 256>>>(cls_, lnf_g, lnf_b, cls_, Bc);
    run_gemm(false, cls_, whead, bhead, nullptr, out,
             Bc, NCc, Dc, Dc, NCc, NCc, 1, 1, 0, 0, 0, 0, 0, 0, 1.0f, 0);
    softmax_kernel<<<Bc, 256>>>(out, Bc, NCc, NCc);
}

// round 3
// speedup vs baseline: 3.9355x; 1.3209x over previous
#include <cuda_runtime.h>
#include <math.h>
#include <stdint.h>

// ---------------- dims ----------------
static const int Lc = 12, Hc = 12, Dc = 768, HDc = 64, Mc = 3072;
static const int IMGc = 384, Bc = 32, NCc = 1000;
static const int NP = 576;            // patches
static const int Sc = 577;            // seq len
static const int BS = Bc * Sc;        // 18464
static const int GRID24 = 24;
static const int KTW = 640;           // padded key width for kT (10*64)

// ---------------- scratch ----------------
__device__ float g_t[BS * Dc];
__device__ float g_h[BS * Dc];
__device__ float g_om[BS * Dc];
__device__ float g_qkv[BS * 3 * Dc];
__device__ float g_mbuf[BS * Mc];
__device__ float g_col[Bc * NP * Dc];
__device__ float g_wtqkv[Lc * Dc * 3 * Dc];
__device__ float g_cwt[Dc * Dc];
__device__ float g_cls[Bc * Dc];
__device__ float g_kT[(long long)Bc * Hc * HDc * KTW];
__device__ float g_wmsar[Lc * Dc * Dc];
__device__ float g_w1r[Lc * Dc * Mc];
__device__ float g_w2r[Lc * Mc * Dc];
__device__ float g_whr[Dc * NCc];

// ---------------- tf32 helpers ----------------
__device__ __forceinline__ uint32_t f2tf(float f) {
    uint32_t u;
    asm("cvt.rna.tf32.f32 %0, %1;" : "=r"(u) : "f"(f));
    return u;
}
__device__ __forceinline__ float f2tf_f(float f) { return __uint_as_float(f2tf(f)); }

__device__ __forceinline__ void mma_tf32(float c[4], const uint32_t a[4], const uint32_t b[2]) {
    asm volatile(
        "mma.sync.aligned.m16n8k8.row.col.f32.tf32.tf32.f32 "
        "{%0,%1,%2,%3}, {%4,%5,%6,%7}, {%8,%9}, {%0,%1,%2,%3};\n"
        : "+f"(c[0]), "+f"(c[1]), "+f"(c[2]), "+f"(c[3])
        : "r"(a[0]), "r"(a[1]), "r"(a[2]), "r"(a[3]), "r"(b[0]), "r"(b[1]));
}

__device__ __forceinline__ void cp_async16(void* smem_dst, const void* gsrc, int sz) {
    unsigned sm = (unsigned)__cvta_generic_to_shared(smem_dst);
    asm volatile("cp.async.ca.shared.global [%0], [%1], 16, %2;\n" :: "r"(sm), "l"(gsrc), "r"(sz));
}

// ---------------- dense tf32 GEMM (inputs pre-rounded to tf32) ----------------
// C[M,N] = act( A@B + bias + res );  optional tf32-round on output.
__global__ void __launch_bounds__(256)
mma_gemm_kernel(const float* __restrict__ A, const float* __restrict__ Bm,
                const float* __restrict__ bias, const float* __restrict__ res,
                float* __restrict__ C,
                int M, int N, int K, int lda, int ldb, int ldc,
                int act, int rnd) {
    __shared__ float As[2][128][20];
    __shared__ float Bs[2][16][136];

    int t = threadIdx.x;
    int lane = t & 31, wid = t >> 5;
    int wm = wid >> 2, wn = wid & 3;
    int g = lane >> 2, tig = lane & 3;
    int m0 = blockIdx.y * 128, n0 = blockIdx.x * 128;

    float acc[4][4][4] = {};
    int nk = K / 16;

    auto loadA = [&](int k0, int buf) {
#pragma unroll
        for (int i = 0; i < 2; i++) {
            int c = t + i * 256;
            int m = c >> 2, kq = (c & 3) * 4;
            const float* src = A + (long long)(m0 + m) * lda + k0 + kq;
            int sz = (m0 + m < M) ? 16 : 0;
            cp_async16(&As[buf][m][kq], src, sz);
        }
    };
    auto loadB = [&](int k0, int buf) {
#pragma unroll
        for (int i = 0; i < 2; i++) {
            int c = t + i * 256;
            int k = c >> 5, nq = (c & 31) * 4;
            const float* src = Bm + (long long)(k0 + k) * ldb + n0 + nq;
            int sz = (n0 + nq < N) ? 16 : 0;
            cp_async16(&Bs[buf][k][nq], src, sz);
        }
    };

    loadA(0, 0);
    loadB(0, 0);
    asm volatile("cp.async.commit_group;\n");
    asm volatile("cp.async.wait_group 0;\n");
    __syncthreads();

    for (int it = 0; it < nk; it++) {
        int buf = it & 1;
        if (it + 1 < nk) {
            loadA((it + 1) * 16, buf ^ 1);
            loadB((it + 1) * 16, buf ^ 1);
            asm volatile("cp.async.commit_group;\n");
        }
#pragma unroll
        for (int ks = 0; ks < 2; ks++) {
            int kk = ks * 8;
            uint32_t af[4][4], bf[4][2];
#pragma unroll
            for (int mt = 0; mt < 4; mt++) {
                int mr = wm * 64 + mt * 16 + g;
                af[mt][0] = __float_as_uint(As[buf][mr][kk + tig]);
                af[mt][1] = __float_as_uint(As[buf][mr + 8][kk + tig]);
                af[mt][2] = __float_as_uint(As[buf][mr][kk + tig + 4]);
                af[mt][3] = __float_as_uint(As[buf][mr + 8][kk + tig + 4]);
            }
#pragma unroll
            for (int nt = 0; nt < 4; nt++) {
                int nc = wn * 32 + nt * 8 + g;
                bf[nt][0] = __float_as_uint(Bs[buf][kk + tig][nc]);
                bf[nt][1] = __float_as_uint(Bs[buf][kk + tig + 4][nc]);
            }
#pragma unroll
            for (int mt = 0; mt < 4; mt++)
#pragma unroll
                for (int nt = 0; nt < 4; nt++)
                    mma_tf32(acc[mt][nt], af[mt], bf[nt]);
        }
        asm volatile("cp.async.wait_group 0;\n");
        __syncthreads();
    }

#pragma unroll
    for (int mt = 0; mt < 4; mt++) {
#pragma unroll
        for (int nt = 0; nt < 4; nt++) {
            int row = m0 + wm * 64 + mt * 16 + g;
            int col = n0 + wn * 32 + nt * 8 + tig * 2;
#pragma unroll
            for (int cc = 0; cc < 4; cc++) {
                int m = row + (cc >> 1) * 8;
                int n = col + (cc & 1);
                if (m >= M || n >= N) continue;
                float v = acc[mt][nt][cc];
                if (bias) v += bias[n];
                if (res) v += res[(long long)m * ldc + n];
                if (act == 1) v = 0.5f * v * (1.0f + erff(v * 0.7071067811865476f));
                if (rnd) v = f2tf_f(v);
                C[(long long)m * ldc + n] = v;
            }
        }
    }
}

// ---------------- fused flash attention ----------------
// grid (qtile=5, H, B), 256 threads (8 warps x 16 q-rows). inputs tf32-pre-rounded.
__global__ void __launch_bounds__(256)
flash_kernel(const float* __restrict__ qkv, const float* __restrict__ kT,
             float* __restrict__ om) {
    extern __shared__ float smf[];
    float* Qs = smf;               // [128][68]
    float* Ps = smf + 8704;        // [8][16][68]
    float* Ks = smf + 17408;       // [2][64][72]  (indexed [hd][key])
    float* Vs = smf + 26624;       // [2][64][72]  (indexed [key][hd])

    int qt = blockIdx.x, h = blockIdx.y, b = blockIdx.z;
    int t = threadIdx.x, lane = t & 31, w = t >> 5, g = lane >> 2, tig = lane & 3;
    const float* qb = qkv + (long long)b * Sc * 2304 + h * 192;
    const float* kb = kT + ((long long)(b * Hc + h)) * HDc * KTW;

    // Q tile 128x64
#pragma unroll
    for (int i = 0; i < 8; i++) {
        int idx = t + i * 256;
        int row = idx >> 4, c4 = (idx & 15) * 4;
        int gr = qt * 128 + row;
        cp_async16(&Qs[row * 68 + c4], qb + (long long)gr * 2304 + c4, gr < Sc ? 16 : 0);
    }
    auto issueK = [&](int kt_, int buf) {
#pragma unroll
        for (int i = 0; i < 4; i++) {
            int idx = t + i * 256;
            int hd = idx >> 4, c4 = (idx & 15) * 4;
            cp_async16(&Ks[(buf * 64 + hd) * 72 + c4], kb + hd * KTW + kt_ * 64 + c4, 16);
        }
    };
    auto issueV = [&](int kt_, int buf) {
#pragma unroll
        for (int i = 0; i < 4; i++) {
            int idx = t + i * 256;
            int row = idx >> 4, c4 = (idx & 15) * 4;
            int gk = kt_ * 64 + row;
            cp_async16(&Vs[(buf * 64 + row) * 72 + c4],
                       qb + (long long)gk * 2304 + 128 + c4, gk < Sc ? 16 : 0);
        }
    };
    issueK(0, 0);
    issueV(0, 0);
    asm volatile("cp.async.commit_group;\n");

    float accO[8][4] = {};
    float mr0 = -1e30f, mr1 = -1e30f, lr0 = 0.f, lr1 = 0.f;
    float* Pw = Ps + w * 16 * 68;
    const int nt = (Sc + 63) / 64;   // 10

    for (int kt_ = 0; kt_ < nt; kt_++) {
        int buf = kt_ & 1;
        __syncthreads();                        // prior compute done -> buf^1 free
        if (kt_ + 1 < nt) { issueK(kt_ + 1, buf ^ 1); issueV(kt_ + 1, buf ^ 1); }
        asm volatile("cp.async.commit_group;\n");
        asm volatile("cp.async.wait_group 1;\n");
        __syncthreads();                        // current tile visible

        // S = Q @ K^T (warp: 16 q-rows x 64 keys)
        float s[8][4] = {};
        const float* Kb = Ks + buf * 64 * 72;
#pragma unroll
        for (int ks = 0; ks < 8; ks++) {
            int kk = ks * 8;
            uint32_t af[4];
            af[0] = __float_as_uint(Qs[(w * 16 + g) * 68 + kk + tig]);
            af[1] = __float_as_uint(Qs[(w * 16 + g + 8) * 68 + kk + tig]);
            af[2] = __float_as_uint(Qs[(w * 16 + g) * 68 + kk + tig + 4]);
            af[3] = __float_as_uint(Qs[(w * 16 + g + 8) * 68 + kk + tig + 4]);
#pragma unroll
            for (int nf = 0; nf < 8; nf++) {
                uint32_t bf[2];
                bf[0] = __float_as_uint(Kb[(kk + tig) * 72 + nf * 8 + g]);
                bf[1] = __float_as_uint(Kb[(kk + tig + 4) * 72 + nf * 8 + g]);
                mma_tf32(s[nf], af, bf);
            }
        }
        // scale + mask
        float rm0 = -1e30f, rm1 = -1e30f;
#pragma unroll
        for (int nf = 0; nf < 8; nf++) {
#pragma unroll
            for (int cc = 0; cc < 4; cc++) {
                int col = kt_ * 64 + nf * 8 + tig * 2 + (cc & 1);
                float v = s[nf][cc] * 0.125f;
                v = (col < Sc) ? v : -1e30f;
                s[nf][cc] = v;
                if (cc < 2) rm0 = fmaxf(rm0, v); else rm1 = fmaxf(rm1, v);
            }
        }
        rm0 = fmaxf(rm0, __shfl_xor_sync(0xffffffffu, rm0, 1));
        rm0 = fmaxf(rm0, __shfl_xor_sync(0xffffffffu, rm0, 2));
        rm1 = fmaxf(rm1, __shfl_xor_sync(0xffffffffu, rm1, 1));
        rm1 = fmaxf(rm1, __shfl_xor_sync(0xffffffffu, rm1, 2));
        float nm0 = fmaxf(mr0, rm0), nm1 = fmaxf(mr1, rm1);
        float cor0 = __expf(mr0 - nm0), cor1 = __expf(mr1 - nm1);
        float rs0 = 0.f, rs1 = 0.f;
#pragma unroll
        for (int nf = 0; nf < 8; nf++) {
            int colb = nf * 8 + tig * 2;
            float p0 = __expf(s[nf][0] - nm0);
            float p1 = __expf(s[nf][1] - nm0);
            float p2 = __expf(s[nf][2] - nm1);
            float p3 = __expf(s[nf][3] - nm1);
            rs0 += p0 + p1; rs1 += p2 + p3;
            Pw[g * 68 + colb]       = f2tf_f(p0);
            Pw[g * 68 + colb + 1]   = f2tf_f(p1);
            Pw[(g + 8) * 68 + colb]     = f2tf_f(p2);
            Pw[(g + 8) * 68 + colb + 1] = f2tf_f(p3);
        }
        rs0 += __shfl_xor_sync(0xffffffffu, rs0, 1);
        rs0 += __shfl_xor_sync(0xffffffffu, rs0, 2);
        rs1 += __shfl_xor_sync(0xffffffffu, rs1, 1);
        rs1 += __shfl_xor_sync(0xffffffffu, rs1, 2);
        lr0 = lr0 * cor0 + rs0;
        lr1 = lr1 * cor1 + rs1;
        mr0 = nm0; mr1 = nm1;
#pragma unroll
        for (int nf = 0; nf < 8; nf++) {
            accO[nf][0] *= cor0; accO[nf][1] *= cor0;
            accO[nf][2] *= cor1; accO[nf][3] *= cor1;
        }
        __syncwarp();
        // O += P @ V
        const float* Vb = Vs + buf * 64 * 72;
#pragma unroll
        for (int ks = 0; ks < 8; ks++) {
            int kk = ks * 8;
            uint32_t af[4];
            af[0] = __float_as_uint(Pw[g * 68 + kk + tig]);
            af[1] = __float_as_uint(Pw[(g + 8) * 68 + kk + tig]);
            af[2] = __float_as_uint(Pw[g * 68 + kk + tig + 4]);
            af[3] = __float_as_uint(Pw[(g + 8) * 68 + kk + tig + 4]);
#pragma unroll
            for (int nf = 0; nf < 8; nf++) {
                uint32_t bf[2];
                bf[0] = __float_as_uint(Vb[(kk + tig) * 72 + nf * 8 + g]);
                bf[1] = __float_as_uint(Vb[(kk + tig + 4) * 72 + nf * 8 + g]);
                mma_tf32(accO[nf], af, bf);
            }
        }
    }

    float inv0 = 1.0f / lr0, inv1 = 1.0f / lr1;
    int r0 = qt * 128 + w * 16 + g;
    int r1 = r0 + 8;
#pragma unroll
    for (int nf = 0; nf < 8; nf++) {
        int colb = nf * 8 + tig * 2;
        if (r0 < Sc) {
            om[((long long)b * Sc + r0) * Dc + h * 64 + colb]     = f2tf_f(accO[nf][0] * inv0);
            om[((long long)b * Sc + r0) * Dc + h * 64 + colb + 1] = f2tf_f(accO[nf][1] * inv0);
        }
        if (r1 < Sc) {
            om[((long long)b * Sc + r1) * Dc + h * 64 + colb]     = f2tf_f(accO[nf][2] * inv1);
            om[((long long)b * Sc + r1) * Dc + h * 64 + colb + 1] = f2tf_f(accO[nf][3] * inv1);
        }
    }
}

// ---------------- K transpose: qkv K-part -> kT[bh][hd][key], key padded to 640 ----------------
__global__ void ktrans_kernel(const float* __restrict__ qkv, float* __restrict__ kT) {
    __shared__ float tile[32][33];
    int ktile = blockIdx.x;        // 0..19
    int hdt = blockIdx.y;          // 0..1
    int bh = blockIdx.z;           // 0..383
    int b = bh / Hc, h = bh % Hc;
    int tx = threadIdx.x, ty = threadIdx.y;   // 32 x 8
#pragma unroll
    for (int j = 0; j < 4; j++) {
        int key = ktile * 32 + ty + j * 8;
        int hd = hdt * 32 + tx;
        float v = 0.f;
        if (key < Sc) v = qkv[((long long)b * Sc + key) * 2304 + h * 192 + 64 + hd];
        tile[ty + j * 8][tx] = v;
    }
    __syncthreads();
#pragma unroll
    for (int j = 0; j < 4; j++) {
        int hd = hdt * 32 + ty + j * 8;
        int key = ktile * 32 + tx;
        kT[((long long)bh * HDc + hd) * KTW + key] = tile[tx][ty + j * 8];
    }
}

// ---------------- aux kernels ----------------
__global__ void im2col_kernel(const float* __restrict__ x, float* __restrict__ col) {
    long long idx = (long long)blockIdx.x * blockDim.x + threadIdx.x;
    long long total = (long long)Bc * NP * Dc;
    if (idx >= total) return;
    int k = (int)(idx % Dc);
    int rem = (int)(idx / Dc);
    int p = rem % NP;
    int b = rem / NP;
    int ph = p / GRID24, pw = p % GRID24;
    int ci = k / 256, k2 = k % 256;
    int kh = k2 / 16, kw = k2 % 16;
    col[idx] = f2tf_f(x[(((long long)b * 3 + ci) * IMGc + ph * 16 + kh) * IMGc + pw * 16 + kw]);
}

__global__ void transpose_convw_kernel(const float* __restrict__ w, float* __restrict__ wt) {
    int idx = blockIdx.x * blockDim.x + threadIdx.x;
    if (idx >= Dc * Dc) return;
    int k = idx / Dc, c = idx % Dc;
    wt[idx] = f2tf_f(w[c * Dc + k]);
}

__global__ void transpose_wqkv_kernel(const float* __restrict__ w, float* __restrict__ wt) {
    long long idx = (long long)blockIdx.x * blockDim.x + threadIdx.x;
    long long total = (long long)Lc * Dc * 3 * Dc;
    if (idx >= total) return;
    int n = (int)(idx % (3 * Dc));
    int rem = (int)(idx / (3 * Dc));
    int d = rem % Dc;
    int l = rem / Dc;
    int h = n / 192, e = n % 192;
    wt[idx] = f2tf_f(w[(((long long)l * Hc + h) * Dc + d) * 192 + e]);
}

__global__ void round_copy_kernel(const float* __restrict__ w, float* __restrict__ o, long long n) {
    long long i = (long long)blockIdx.x * blockDim.x + threadIdx.x;
    if (i < n) o[i] = f2tf_f(w[i]);
}

__global__ void embed_kernel(const float* __restrict__ pout, const float* __restrict__ cls,
                             const float* __restrict__ pos, float* __restrict__ t) {
    long long idx = (long long)blockIdx.x * blockDim.x + threadIdx.x;
    long long total = (long long)Bc * Sc * Dc;
    if (idx >= total) return;
    int j = (int)(idx % Dc);
    int rem = (int)(idx / Dc);
    int r = rem % Sc;
    int b = rem / Sc;
    float v;
    if (r == 0) {
        v = cls[j];
    } else {
        int i = (r - 1) * Dc + j;
        int c = i / NP, p = i % NP;
        v = pout[((long long)b * NP + p) * Dc + c];
    }
    t[idx] = v + pos[r * Dc + j];
}

__global__ void layernorm_kernel(const float* __restrict__ x, const float* __restrict__ g,
                                 const float* __restrict__ b, float* __restrict__ y, int rows) {
    __shared__ float red[256];
    int row = blockIdx.x;
    if (row >= rows) return;
    int t = threadIdx.x;
    const float* xr = x + (long long)row * Dc;
    float v[3];
    float s = 0.f;
#pragma unroll
    for (int i = 0; i < 3; i++) { v[i] = xr[t + i * 256]; s += v[i]; }
    red[t] = s; __syncthreads();
    for (int o = 128; o > 0; o >>= 1) { if (t < o) red[t] += red[t + o]; __syncthreads(); }
    float mu = red[0] / Dc;
    __syncthreads();
    float s2 = 0.f;
#pragma unroll
    for (int i = 0; i < 3; i++) { float d = v[i] - mu; s2 += d * d; }
    red[t] = s2; __syncthreads();
    for (int o = 128; o > 0; o >>= 1) { if (t < o) red[t] += red[t + o]; __syncthreads(); }
    float rstd = rsqrtf(red[0] / Dc + 1e-5f);
    float* yr = y + (long long)row * Dc;
#pragma unroll
    for (int i = 0; i < 3; i++) {
        int j = t + i * 256;
        yr[j] = f2tf_f((v[i] - mu) * rstd * g[j] + b[j]);
    }
}

__global__ void softmax_kernel(float* __restrict__ x, long long rows, int n) {
    __shared__ float red[256];
    long long row = blockIdx.x;
    if (row >= rows) return;
    int t = threadIdx.x;
    float* xr = x + row * n;
    float lmax = -1e30f;
    for (int j = t; j < n; j += 256) lmax = fmaxf(lmax, xr[j]);
    red[t] = lmax; __syncthreads();
    for (int o = 128; o > 0; o >>= 1) { if (t < o) red[t] = fmaxf(red[t], red[t + o]); __syncthreads(); }
    float mx = red[0];
    __syncthreads();
    float ls = 0.f;
    for (int j = t; j < n; j += 256) { float e = expf(xr[j] - mx); xr[j] = e; ls += e; }
    red[t] = ls; __syncthreads();
    for (int o = 128; o > 0; o >>= 1) { if (t < o) red[t] += red[t + o]; __syncthreads(); }
    float inv = 1.0f / red[0];
    for (int j = t; j < n; j += 256) xr[j] *= inv;
}

__global__ void extract_cls_kernel(const float* __restrict__ t, float* __restrict__ cls) {
    int idx = blockIdx.x * blockDim.x + threadIdx.x;
    if (idx >= Bc * Dc) return;
    int b = idx / Dc, j = idx % Dc;
    cls[idx] = t[((long long)b * Sc) * Dc + j];
}

// ---------------- host helpers ----------------
static void run_gemm(const float* A, const float* Bm, const float* bias,
                     const float* res, float* C, int M, int N, int K,
                     int lda, int ldb, int ldc, int act, int rnd) {
    dim3 grid((N + 127) / 128, (M + 127) / 128, 1);
    mma_gemm_kernel<<<grid, 256>>>(A, Bm, bias, res, C, M, N, K, lda, ldb, ldc, act, rnd);
}

extern "C" void kernel_launch(void* const* d_in, const int* in_sizes, int n_in,
                              void* d_out, int out_size) {
    const float* x       = (const float*)d_in[0];
    const float* conv_w  = (const float*)d_in[1];
    const float* conv_b  = (const float*)d_in[2];
    const float* cls_tok = (const float*)d_in[3];
    const float* pos_emb = (const float*)d_in[4];
    const float* ln1_g   = (const float*)d_in[5];
    const float* ln1_b   = (const float*)d_in[6];
    const float* wqkv    = (const float*)d_in[7];
    const float* bqkv    = (const float*)d_in[8];
    const float* wmsa    = (const float*)d_in[9];
    const float* bmsa    = (const float*)d_in[10];
    const float* ln2_g   = (const float*)d_in[11];
    const float* ln2_b   = (const float*)d_in[12];
    const float* lnm_g   = (const float*)d_in[13];
    const float* lnm_b   = (const float*)d_in[14];
    const float* w1      = (const float*)d_in[15];
    const float* b1      = (const float*)d_in[16];
    const float* w2      = (const float*)d_in[17];
    const float* b2      = (const float*)d_in[18];
    const float* lnf_g   = (const float*)d_in[19];
    const float* lnf_b   = (const float*)d_in[20];
    const float* whead   = (const float*)d_in[21];
    const float* bhead   = (const float*)d_in[22];
    float* out = (float*)d_out;

    float *t_, *h_, *om_, *qkv_, *mb_, *col_, *wtq_, *cwt_, *cls_, *kT_;
    float *wmsar_, *w1r_, *w2r_, *whr_;
    cudaGetSymbolAddress((void**)&t_,  g_t);
    cudaGetSymbolAddress((void**)&h_,  g_h);
    cudaGetSymbolAddress((void**)&om_, g_om);
    cudaGetSymbolAddress((void**)&qkv_, g_qkv);
    cudaGetSymbolAddress((void**)&mb_, g_mbuf);
    cudaGetSymbolAddress((void**)&col_, g_col);
    cudaGetSymbolAddress((void**)&wtq_, g_wtqkv);
    cudaGetSymbolAddress((void**)&cwt_, g_cwt);
    cudaGetSymbolAddress((void**)&cls_, g_cls);
    cudaGetSymbolAddress((void**)&kT_, g_kT);
    cudaGetSymbolAddress((void**)&wmsar_, g_wmsar);
    cudaGetSymbolAddress((void**)&w1r_, g_w1r);
    cudaGetSymbolAddress((void**)&w2r_, g_w2r);
    cudaGetSymbolAddress((void**)&whr_, g_whr);

    cudaFuncSetAttribute(flash_kernel, cudaFuncAttributeMaxDynamicSharedMemorySize, 143360);

    // --- weight re-layouts / tf32 pre-rounding ---
    transpose_convw_kernel<<<(Dc * Dc + 255) / 256, 256>>>(conv_w, cwt_);
    {
        long long tot = (long long)Lc * Dc * 3 * Dc;
        transpose_wqkv_kernel<<<(int)((tot + 255) / 256), 256>>>(wqkv, wtq_);
    }
    {
        long long n1 = (long long)Lc * Dc * Dc;
        round_copy_kernel<<<(int)((n1 + 255) / 256), 256>>>(wmsa, wmsar_, n1);
        long long n2 = (long long)Lc * Dc * Mc;
        round_copy_kernel<<<(int)((n2 + 255) / 256), 256>>>(w1, w1r_, n2);
        round_copy_kernel<<<(int)((n2 + 255) / 256), 256>>>(w2, w2r_, n2);
        long long n3 = (long long)Dc * NCc;
        round_copy_kernel<<<(int)((n3 + 255) / 256), 256>>>(whead, whr_, n3);
    }

    // --- patchify ---
    {
        long long tot = (long long)Bc * NP * Dc;
        im2col_kernel<<<(int)((tot + 255) / 256), 256>>>(x, col_);
    }
    run_gemm(col_, cwt_, conv_b, nullptr, h_, Bc * NP, Dc, Dc, Dc, Dc, Dc, 0, 0);
    {
        long long tot = (long long)Bc * Sc * Dc;
        embed_kernel<<<(int)((tot + 255) / 256), 256>>>(h_, cls_tok, pos_emb, t_);
    }

    // --- encoder layers ---
    for (int l = 0; l < Lc; l++) {
        layernorm_kernel<<<BS, 256>>>(t_, ln1_g + l * Dc, ln1_b + l * Dc, h_, BS);
        // qkv = h @ Wt[l] + bqkv[l]   (tf32-rounded out)
        run_gemm(h_, wtq_ + (long long)l * Dc * 3 * Dc, bqkv + l * 3 * Dc, nullptr,
                 qkv_, BS, 3 * Dc, Dc, Dc, 3 * Dc, 3 * Dc, 0, 1);
        // K transpose for this layer
        ktrans_kernel<<<dim3(KTW / 32, 2, Bc * Hc), dim3(32, 8)>>>(qkv_, kT_);
        // fused attention -> om (rounded)
        flash_kernel<<<dim3((Sc + 127) / 128, Hc, Bc), 256, 143360>>>(qkv_, kT_, om_);
        // msa: t = om @ wmsa + bmsa + h
        run_gemm(om_, wmsar_ + (long long)l * Dc * Dc, bmsa + l * Dc, h_, t_,
                 BS, Dc, Dc, Dc, Dc, Dc, 0, 0);
        // double LN
        layernorm_kernel<<<BS, 256>>>(t_, ln2_g + l * Dc, ln2_b + l * Dc, h_, BS);
        layernorm_kernel<<<BS, 256>>>(h_, lnm_g + l * Dc, lnm_b + l * Dc, h_, BS);
        // mlp
        run_gemm(h_, w1r_ + (long long)l * Dc * Mc, b1 + l * Mc, nullptr, mb_,
                 BS, Mc, Dc, Dc, Mc, Mc, 1, 1);
        run_gemm(mb_, w2r_ + (long long)l * Mc * Dc, b2 + l * Dc, t_, t_,
                 BS, Dc, Mc, Mc, Dc, Dc, 0, 0);
    }

    // --- head ---
    extract_cls_kernel<<<(Bc * Dc + 255) / 256, 256>>>(t_, cls_);
    layernorm_kernel<<<Bc, 256>>>(cls_, lnf_g, lnf_b, cls_, Bc);
    run_gemm(cls_, whr_, bhead, nullptr, out, Bc, NCc, Dc, Dc, NCc, NCc, 0, 0);
    softmax_kernel<<<Bc, 256>>>(out, Bc, NCc);
}